// round 14
// baseline (speedup 1.0000x reference)
#include <cuda_runtime.h>
#include <cuda_fp16.h>
#include <math.h>
#include <stdint.h>

// Problem shape (fixed by the dataset)
#define BB 16
#define NN 1024
#define HH 1280
#define DD 256
#define EPSV 1e-8f

// Output segment offsets (elements), tuple flattened in order, float32
#define OFF_CH   0LL
#define OFF_NEUT (OFF_CH   + (long long)BB*HH*3)
#define OFF_PC   (OFF_NEUT + (long long)BB*HH*3)
#define OFF_EM   (OFF_PC   + (long long)BB*HH)
#define OFF_MM   (OFF_EM   + (long long)BB*HH)
#define OFF_NFS  (OFF_MM   + (long long)BB*HH*DD)

// Device scratch
__device__ __half g_ah[(size_t)BB*HH*NN];   // pred_inc fp16 [b][h][n]
__device__ __half g_bh[(size_t)BB*DD*NN];   // node_feat fp16 [b][d][n]
#define NSPL 16
__device__ float  g_nfs_part[BB*NSPL*DD];

// ---------------------------------------------------------------------------
// PTX helpers (baseline PTX only)
// ---------------------------------------------------------------------------
__device__ __forceinline__ uint32_t smem_u32(const void* p) {
    return (uint32_t)__cvta_generic_to_shared(p);
}
__device__ __forceinline__ void cp16(uint32_t dst, const void* src) {
    asm volatile("cp.async.cg.shared.global [%0], [%1], 16;"
                 :: "r"(dst), "l"(src) : "memory");
}
__device__ __forceinline__ void cp_commit() {
    asm volatile("cp.async.commit_group;" ::: "memory");
}
template <int N>
__device__ __forceinline__ void cp_wait() {
    asm volatile("cp.async.wait_group %0;" :: "n"(N) : "memory");
}
__device__ __forceinline__ void mma_f16(float* c, const uint32_t* a, const uint32_t* b) {
    asm volatile(
        "mma.sync.aligned.m16n8k16.row.col.f32.f16.f16.f32 "
        "{%0,%1,%2,%3}, {%4,%5,%6,%7}, {%8,%9}, {%0,%1,%2,%3};"
        : "+f"(c[0]), "+f"(c[1]), "+f"(c[2]), "+f"(c[3])
        : "r"(a[0]), "r"(a[1]), "r"(a[2]), "r"(a[3]), "r"(b[0]), "r"(b[1]));
}
#define LDSM_X4(r0, r1, r2, r3, addr) \
    asm volatile("ldmatrix.sync.aligned.m8n8.x4.shared.b16 {%0,%1,%2,%3}, [%4];" \
                 : "=r"(r0), "=r"(r1), "=r"(r2), "=r"(r3) : "r"(addr))

// ---------------------------------------------------------------------------
// 1) Transpose node_feat [b,n,d] -> g_bh fp16 [b,d,n]; fused nfs partials.
// ---------------------------------------------------------------------------
__global__ void transpose_kernel(const float* __restrict__ nf) {
    __shared__ float tile[64][33];
    int b  = blockIdx.z;
    int n0 = blockIdx.x * 64;
    int d0 = blockIdx.y * 32;
    int tx = threadIdx.x, ty = threadIdx.y;  // (32, 8)
    const float* src = nf + (size_t)b * NN * DD;
    #pragma unroll
    for (int j = 0; j < 8; j++)
        tile[ty + j * 8][tx] = src[(size_t)(n0 + ty + j * 8) * DD + d0 + tx];
    __syncthreads();
    __half* dst = g_bh + (size_t)b * DD * NN;
    #pragma unroll
    for (int j = 0; j < 4; j++) {
        int d = d0 + ty + j * 8;
        __half2 v = __floats2half2_rn(tile[2 * tx][ty + j * 8],
                                      tile[2 * tx + 1][ty + j * 8]);
        *(__half2*)(dst + (size_t)d * NN + n0 + 2 * tx) = v;
    }
    if (ty == 0) {
        float s = 0.f;
        #pragma unroll
        for (int i = 0; i < 64; i++) s += tile[i][tx];
        g_nfs_part[((size_t)b * NSPL + (n0 >> 6)) * DD + d0 + tx] = s;
    }
}

__global__ void nfs_final_kernel(float* __restrict__ out) {
    int b = blockIdx.x, d = threadIdx.x;
    float s = 0.f;
    #pragma unroll
    for (int t = 0; t < NSPL; t++) s += g_nfs_part[((size_t)b * NSPL + t) * DD + d];
    out[OFF_NFS + (size_t)b * DD + d] = s;
}

// ---------------------------------------------------------------------------
// 2) Row reductions (fp32 FFMA); weights computed in-block from raw inputs
//    and staged in SMEM; emits fp16 pred_inc. 16 rows/block, 256 threads.
// ---------------------------------------------------------------------------
__global__ __launch_bounds__(256, 5)
void row_kernel(const float* __restrict__ pred_inc,
                const float* __restrict__ e_raw,
                const float* __restrict__ eta_raw,
                const float* __restrict__ phi,
                const float* __restrict__ em_frac,
                const int*   __restrict__ is_topo,
                const float* __restrict__ track_pt,
                const float* __restrict__ track_eta,
                const float* __restrict__ track_phi,
                const int*   __restrict__ is_track,
                float* __restrict__ out) {
    __shared__ float sw[5][NN];

    int tid  = threadIdx.x;
    int lane = tid & 31;
    int wid  = tid >> 5;
    int b    = blockIdx.y;
    int row0 = b * HH + blockIdx.x * 16 + wid * 2;

    {
        int base = b * NN + tid * 4;
        float4 e  = *(const float4*)(e_raw   + base);
        float4 et = *(const float4*)(eta_raw + base);
        float4 ph = *(const float4*)(phi     + base);
        float4 em = *(const float4*)(em_frac + base);
        int4   it = *(const int4*)  (is_topo + base);
        float ws[4] = { e.x * (float)it.x, e.y * (float)it.y,
                        e.z * (float)it.z, e.w * (float)it.w };
        float ev[4] = { et.x, et.y, et.z, et.w };
        float pv[4] = { ph.x, ph.y, ph.z, ph.w };
        float mv[4] = { em.x, em.y, em.z, em.w };
        #pragma unroll
        for (int k = 0; k < 4; k++) {
            float sn, cs;
            sincosf(pv[k], &sn, &cs);
            int n = tid * 4 + k;
            sw[0][n] = ws[k];
            sw[1][n] = ws[k] * ev[k];
            sw[2][n] = ws[k] * sn;
            sw[3][n] = ws[k] * cs;
            sw[4][n] = ws[k] * mv[k];
        }
    }
    __syncthreads();

    const float4* p4 = (const float4*)(pred_inc + (size_t)row0 * NN);
    const float4* q4 = (const float4*)(pred_inc + (size_t)(row0 + 1) * NN);
    uint2* hp = (uint2*)(g_ah + (size_t)row0 * NN);
    uint2* hq = (uint2*)(g_ah + (size_t)(row0 + 1) * NN);

    float a0 = 0.f, a1 = 0.f, a2 = 0.f, a3 = 0.f, a4 = 0.f;
    float b0 = 0.f, b1 = 0.f, b2 = 0.f, b3 = 0.f, b4 = 0.f;
    #pragma unroll 4
    for (int i = lane; i < NN / 4; i += 32) {
        float4 p = p4[i];
        float4 q = q4[i];
        {
            __half2 h0 = __floats2half2_rn(p.x, p.y);
            __half2 h1 = __floats2half2_rn(p.z, p.w);
            uint2 st;
            st.x = *(uint32_t*)&h0; st.y = *(uint32_t*)&h1;
            hp[i] = st;
            __half2 g0 = __floats2half2_rn(q.x, q.y);
            __half2 g1 = __floats2half2_rn(q.z, q.w);
            st.x = *(uint32_t*)&g0; st.y = *(uint32_t*)&g1;
            hq[i] = st;
        }
        float4 w = *(const float4*)&sw[0][i * 4];
        a0 = fmaf(p.x, w.x, a0); a0 = fmaf(p.y, w.y, a0);
        a0 = fmaf(p.z, w.z, a0); a0 = fmaf(p.w, w.w, a0);
        b0 = fmaf(q.x, w.x, b0); b0 = fmaf(q.y, w.y, b0);
        b0 = fmaf(q.z, w.z, b0); b0 = fmaf(q.w, w.w, b0);
        float4 e = *(const float4*)&sw[1][i * 4];
        a1 = fmaf(p.x, e.x, a1); a1 = fmaf(p.y, e.y, a1);
        a1 = fmaf(p.z, e.z, a1); a1 = fmaf(p.w, e.w, a1);
        b1 = fmaf(q.x, e.x, b1); b1 = fmaf(q.y, e.y, b1);
        b1 = fmaf(q.z, e.z, b1); b1 = fmaf(q.w, e.w, b1);
        float4 s = *(const float4*)&sw[2][i * 4];
        a2 = fmaf(p.x, s.x, a2); a2 = fmaf(p.y, s.y, a2);
        a2 = fmaf(p.z, s.z, a2); a2 = fmaf(p.w, s.w, a2);
        b2 = fmaf(q.x, s.x, b2); b2 = fmaf(q.y, s.y, b2);
        b2 = fmaf(q.z, s.z, b2); b2 = fmaf(q.w, s.w, b2);
        float4 c = *(const float4*)&sw[3][i * 4];
        a3 = fmaf(p.x, c.x, a3); a3 = fmaf(p.y, c.y, a3);
        a3 = fmaf(p.z, c.z, a3); a3 = fmaf(p.w, c.w, a3);
        b3 = fmaf(q.x, c.x, b3); b3 = fmaf(q.y, c.y, b3);
        b3 = fmaf(q.z, c.z, b3); b3 = fmaf(q.w, c.w, b3);
        float4 m = *(const float4*)&sw[4][i * 4];
        a4 = fmaf(p.x, m.x, a4); a4 = fmaf(p.y, m.y, a4);
        a4 = fmaf(p.z, m.z, a4); a4 = fmaf(p.w, m.w, a4);
        b4 = fmaf(q.x, m.x, b4); b4 = fmaf(q.y, m.y, b4);
        b4 = fmaf(q.z, m.z, b4); b4 = fmaf(q.w, m.w, b4);
    }
    #pragma unroll
    for (int o = 16; o > 0; o >>= 1) {
        a0 += __shfl_xor_sync(0xFFFFFFFFu, a0, o);
        a1 += __shfl_xor_sync(0xFFFFFFFFu, a1, o);
        a2 += __shfl_xor_sync(0xFFFFFFFFu, a2, o);
        a3 += __shfl_xor_sync(0xFFFFFFFFu, a3, o);
        a4 += __shfl_xor_sync(0xFFFFFFFFu, a4, o);
        b0 += __shfl_xor_sync(0xFFFFFFFFu, b0, o);
        b1 += __shfl_xor_sync(0xFFFFFFFFu, b1, o);
        b2 += __shfl_xor_sync(0xFFFFFFFFu, b2, o);
        b3 += __shfl_xor_sync(0xFFFFFFFFu, b3, o);
        b4 += __shfl_xor_sync(0xFFFFFFFFu, b4, o);
    }
    if (lane == 0) {
        #pragma unroll
        for (int rr = 0; rr < 2; rr++) {
            int   row = row0 + rr;
            int   h   = row % HH;
            float s0  = rr ? b0 : a0;
            float s1  = rr ? b1 : a1;
            float s2  = rr ? b2 : a2;
            float s3  = rr ? b3 : a3;
            float s4v = rr ? b4 : a4;

            float inv = 1.f / (s0 + EPSV);
            bool  pc  = (h < NN) && (is_track[b * NN + h] != 0);
            float nm  = pc ? 0.f : 1.f;

            float ke  = log1pf(fmaxf(s0, 0.f));
            float eta = s1 * inv * (1.f / 3.0f);
            float ph  = atan2f(s2 * inv, s3 * inv);
            float em  = s4v * inv;

            long long r3 = (long long)row * 3;
            float cpt = 0.f, ceta = 0.f, cphi = 0.f;
            if (pc) {
                cpt  = track_pt [b * NN + h];
                ceta = track_eta[b * NN + h];
                cphi = track_phi[b * NN + h];
            }
            out[OFF_CH + r3 + 0] = cpt;
            out[OFF_CH + r3 + 1] = ceta;
            out[OFF_CH + r3 + 2] = cphi;
            out[OFF_NEUT + r3 + 0] = ke  * nm;
            out[OFF_NEUT + r3 + 1] = eta * nm;
            out[OFF_NEUT + r3 + 2] = ph  * nm;
            out[OFF_PC + row] = pc ? 1.f : 0.f;
            out[OFF_EM + row] = em;
        }
    }
}

// ---------------------------------------------------------------------------
// 3) fp16 mma GEMM with ldmatrix: block 128x128, BK=64 halfs, 256 threads
//    (8 warps, 2x4, warp tile 64x32). 2-stage cp.async, 72 KB smem.
//    16 warps/SM (2 CTAs) for latency hiding — tensor pipe was 39% at 8 warps.
// ---------------------------------------------------------------------------
#define BM 128
#define BN 128
#define BKH 64
#define KPAD 72                     // halfs per smem row (144 B)
#define A_H (BM * KPAD)             // 9216 halfs
#define B_H (BN * KPAD)
#define STG_H (A_H + B_H)           // 18432 halfs = 36 KB / stage
#define GEMM_SMEM (2 * STG_H * 2)   // 73728 B

__global__ __launch_bounds__(256, 2)
void gemm_mma_kernel(float* __restrict__ C) {   // [B][H][D]
    extern __shared__ __align__(16) __half smem[];

    int tid  = threadIdx.x;
    int wid  = tid >> 5;      // 0..7
    int lane = tid & 31;
    int gid  = lane >> 2;
    int tig  = lane & 3;
    int warp_m = wid & 1;     // 0..1 (64 rows each)
    int warp_n = wid >> 1;    // 0..3 (32 cols each)
    int q  = lane >> 3;       // ldmatrix quadrant
    int rr = lane & 7;

    int b  = blockIdx.z;
    int m0 = blockIdx.y * BM;
    int n0 = blockIdx.x * BN;

    const __half* Ah = g_ah + ((size_t)b * HH + m0) * NN;
    const __half* Bh = g_bh + ((size_t)b * DD + n0) * NN;

    int lr = tid >> 3;   // 0..31
    int lj = tid & 7;    // 8-half chunk within 64-half row

    uint32_t a_off = (uint32_t)(((warp_m * 64 + (q & 1) * 8 + rr) * KPAD + (q >> 1) * 8) * 2);
    uint32_t b_off = (uint32_t)(((warp_n * 32 + (q >> 1) * 8 + rr) * KPAD + (q & 1) * 8) * 2);

    float acc[4][4][4];
    #pragma unroll
    for (int i = 0; i < 4; i++)
        #pragma unroll
        for (int j = 0; j < 4; j++)
            #pragma unroll
            for (int k = 0; k < 4; k++) acc[i][j][k] = 0.f;

    auto load_tile = [&](int t, int s) {
        __half* asx = smem + s * STG_H;
        __half* bsx = asx + A_H;
        int k0 = t * BKH;
        #pragma unroll
        for (int i = 0; i < 4; i++) {
            int r = lr + i * 32;
            cp16(smem_u32(asx + r * KPAD + lj * 8), Ah + (size_t)r * NN + k0 + lj * 8);
            cp16(smem_u32(bsx + r * KPAD + lj * 8), Bh + (size_t)r * NN + k0 + lj * 8);
        }
        cp_commit();
    };

    load_tile(0, 0);

    const int NT = NN / BKH;  // 16
    for (int t = 0; t < NT; t++) {
        if (t + 1 < NT) {
            load_tile(t + 1, (t + 1) & 1);
            cp_wait<1>();
        } else {
            cp_wait<0>();
        }
        __syncthreads();

        uint32_t as_u = smem_u32(smem + (t & 1) * STG_H);
        uint32_t bs_u = as_u + A_H * 2;

        #pragma unroll
        for (int kk = 0; kk < BKH; kk += 16) {
            uint32_t bf[4][2];
            #pragma unroll
            for (int nf2 = 0; nf2 < 2; nf2++) {
                uint32_t r0, r1, r2, r3;
                LDSM_X4(r0, r1, r2, r3,
                        bs_u + b_off + (uint32_t)((nf2 * 16 * KPAD + kk) * 2));
                bf[2 * nf2][0]     = r0;
                bf[2 * nf2][1]     = r1;
                bf[2 * nf2 + 1][0] = r2;
                bf[2 * nf2 + 1][1] = r3;
            }
            #pragma unroll
            for (int mf = 0; mf < 4; mf++) {
                uint32_t af[4];
                LDSM_X4(af[0], af[1], af[2], af[3],
                        as_u + a_off + (uint32_t)((mf * 16 * KPAD + kk) * 2));
                #pragma unroll
                for (int nf = 0; nf < 4; nf++)
                    mma_f16(acc[mf][nf], af, bf[nf]);
            }
        }
        __syncthreads();
    }

    // Epilogue
    float* Cb = C + ((size_t)b * HH + m0) * DD + n0;
    #pragma unroll
    for (int mf = 0; mf < 4; mf++) {
        int r0 = warp_m * 64 + mf * 16 + gid;
        #pragma unroll
        for (int nf = 0; nf < 4; nf++) {
            int cc = warp_n * 32 + nf * 8 + tig * 2;
            *(float2*)(Cb + (size_t)r0 * DD + cc) =
                make_float2(acc[mf][nf][0], acc[mf][nf][1]);
            *(float2*)(Cb + (size_t)(r0 + 8) * DD + cc) =
                make_float2(acc[mf][nf][2], acc[mf][nf][3]);
        }
    }
}

// ---------------------------------------------------------------------------
extern "C" void kernel_launch(void* const* d_in, const int* in_sizes, int n_in,
                              void* d_out, int out_size) {
    const float* pred_inc  = (const float*)d_in[0];
    const float* node_feat = (const float*)d_in[1];
    const float* e_raw     = (const float*)d_in[2];
    const float* eta_raw   = (const float*)d_in[3];
    const float* phi       = (const float*)d_in[4];
    const float* em_frac   = (const float*)d_in[5];
    const float* track_pt  = (const float*)d_in[6];
    const float* track_eta = (const float*)d_in[7];
    const float* track_phi = (const float*)d_in[8];
    const int*   is_track  = (const int*)d_in[9];
    const int*   is_topo   = (const int*)d_in[10];
    float* out = (float*)d_out;

    cudaFuncSetAttribute(gemm_mma_kernel,
                         cudaFuncAttributeMaxDynamicSharedMemorySize, GEMM_SMEM);

    {
        dim3 grid(NN / 64, DD / 32, BB);
        transpose_kernel<<<grid, dim3(32, 8)>>>(node_feat);
    }
    nfs_final_kernel<<<BB, DD>>>(out);

    {
        dim3 grid(HH / 16, BB);
        row_kernel<<<grid, 256>>>(pred_inc, e_raw, eta_raw, phi, em_frac, is_topo,
                                  track_pt, track_eta, track_phi, is_track, out);
    }

    {
        dim3 grid(DD / BN, HH / BM, BB);
        gemm_mma_kernel<<<grid, 256, GEMM_SMEM>>>(out + OFF_MM);
    }
}

// round 16
// speedup vs baseline: 1.0498x; 1.0498x over previous
#include <cuda_runtime.h>
#include <cuda_fp16.h>
#include <math.h>
#include <stdint.h>

// Problem shape (fixed by the dataset)
#define BB 16
#define NN 1024
#define HH 1280
#define DD 256
#define EPSV 1e-8f

// Output segment offsets (elements), tuple flattened in order, float32
#define OFF_CH   0LL
#define OFF_NEUT (OFF_CH   + (long long)BB*HH*3)
#define OFF_PC   (OFF_NEUT + (long long)BB*HH*3)
#define OFF_EM   (OFF_PC   + (long long)BB*HH)
#define OFF_MM   (OFF_EM   + (long long)BB*HH)
#define OFF_NFS  (OFF_MM   + (long long)BB*HH*DD)

// Device scratch
__device__ __half g_ah[(size_t)BB*HH*NN];   // pred_inc fp16 [b][h][n]
__device__ __half g_bh[(size_t)BB*DD*NN];   // node_feat fp16 [b][d][n]
#define NSPL 16
__device__ float  g_nfs_part[BB*NSPL*DD];

// ---------------------------------------------------------------------------
// PTX helpers (baseline PTX only)
// ---------------------------------------------------------------------------
__device__ __forceinline__ uint32_t smem_u32(const void* p) {
    return (uint32_t)__cvta_generic_to_shared(p);
}
__device__ __forceinline__ void cp16(uint32_t dst, const void* src) {
    asm volatile("cp.async.cg.shared.global [%0], [%1], 16;"
                 :: "r"(dst), "l"(src) : "memory");
}
__device__ __forceinline__ void cp_commit() {
    asm volatile("cp.async.commit_group;" ::: "memory");
}
template <int N>
__device__ __forceinline__ void cp_wait() {
    asm volatile("cp.async.wait_group %0;" :: "n"(N) : "memory");
}
__device__ __forceinline__ void mma_f16(float* c, const uint32_t* a, const uint32_t* b) {
    asm volatile(
        "mma.sync.aligned.m16n8k16.row.col.f32.f16.f16.f32 "
        "{%0,%1,%2,%3}, {%4,%5,%6,%7}, {%8,%9}, {%0,%1,%2,%3};"
        : "+f"(c[0]), "+f"(c[1]), "+f"(c[2]), "+f"(c[3])
        : "r"(a[0]), "r"(a[1]), "r"(a[2]), "r"(a[3]), "r"(b[0]), "r"(b[1]));
}
#define LDSM_X4(r0, r1, r2, r3, addr) \
    asm volatile("ldmatrix.sync.aligned.m8n8.x4.shared.b16 {%0,%1,%2,%3}, [%4];" \
                 : "=r"(r0), "=r"(r1), "=r"(r2), "=r"(r3) : "r"(addr))

// ---------------------------------------------------------------------------
// 1) Transpose node_feat [b,n,d] -> g_bh fp16 [b,d,n]; fused nfs partials.
// ---------------------------------------------------------------------------
__global__ void transpose_kernel(const float* __restrict__ nf) {
    __shared__ float tile[64][33];
    int b  = blockIdx.z;
    int n0 = blockIdx.x * 64;
    int d0 = blockIdx.y * 32;
    int tx = threadIdx.x, ty = threadIdx.y;  // (32, 8)
    const float* src = nf + (size_t)b * NN * DD;
    #pragma unroll
    for (int j = 0; j < 8; j++)
        tile[ty + j * 8][tx] = src[(size_t)(n0 + ty + j * 8) * DD + d0 + tx];
    __syncthreads();
    __half* dst = g_bh + (size_t)b * DD * NN;
    #pragma unroll
    for (int j = 0; j < 4; j++) {
        int d = d0 + ty + j * 8;
        __half2 v = __floats2half2_rn(tile[2 * tx][ty + j * 8],
                                      tile[2 * tx + 1][ty + j * 8]);
        *(__half2*)(dst + (size_t)d * NN + n0 + 2 * tx) = v;
    }
    if (ty == 0) {
        float s = 0.f;
        #pragma unroll
        for (int i = 0; i < 64; i++) s += tile[i][tx];
        g_nfs_part[((size_t)b * NSPL + (n0 >> 6)) * DD + d0 + tx] = s;
    }
}

__global__ void nfs_final_kernel(float* __restrict__ out) {
    int b = blockIdx.x, d = threadIdx.x;
    float s = 0.f;
    #pragma unroll
    for (int t = 0; t < NSPL; t++) s += g_nfs_part[((size_t)b * NSPL + t) * DD + d];
    out[OFF_NFS + (size_t)b * DD + d] = s;
}

// ---------------------------------------------------------------------------
// 2) Row reductions (fp32 FFMA); weights computed in-block from raw inputs
//    and staged in SMEM; emits fp16 pred_inc. 16 rows/block, 256 threads.
// ---------------------------------------------------------------------------
__global__ __launch_bounds__(256, 5)
void row_kernel(const float* __restrict__ pred_inc,
                const float* __restrict__ e_raw,
                const float* __restrict__ eta_raw,
                const float* __restrict__ phi,
                const float* __restrict__ em_frac,
                const int*   __restrict__ is_topo,
                const float* __restrict__ track_pt,
                const float* __restrict__ track_eta,
                const float* __restrict__ track_phi,
                const int*   __restrict__ is_track,
                float* __restrict__ out) {
    __shared__ float sw[5][NN];

    int tid  = threadIdx.x;
    int lane = tid & 31;
    int wid  = tid >> 5;
    int b    = blockIdx.y;
    int row0 = b * HH + blockIdx.x * 16 + wid * 2;

    {
        int base = b * NN + tid * 4;
        float4 e  = *(const float4*)(e_raw   + base);
        float4 et = *(const float4*)(eta_raw + base);
        float4 ph = *(const float4*)(phi     + base);
        float4 em = *(const float4*)(em_frac + base);
        int4   it = *(const int4*)  (is_topo + base);
        float ws[4] = { e.x * (float)it.x, e.y * (float)it.y,
                        e.z * (float)it.z, e.w * (float)it.w };
        float ev[4] = { et.x, et.y, et.z, et.w };
        float pv[4] = { ph.x, ph.y, ph.z, ph.w };
        float mv[4] = { em.x, em.y, em.z, em.w };
        #pragma unroll
        for (int k = 0; k < 4; k++) {
            float sn, cs;
            sincosf(pv[k], &sn, &cs);
            int n = tid * 4 + k;
            sw[0][n] = ws[k];
            sw[1][n] = ws[k] * ev[k];
            sw[2][n] = ws[k] * sn;
            sw[3][n] = ws[k] * cs;
            sw[4][n] = ws[k] * mv[k];
        }
    }
    __syncthreads();

    const float4* p4 = (const float4*)(pred_inc + (size_t)row0 * NN);
    const float4* q4 = (const float4*)(pred_inc + (size_t)(row0 + 1) * NN);
    uint2* hp = (uint2*)(g_ah + (size_t)row0 * NN);
    uint2* hq = (uint2*)(g_ah + (size_t)(row0 + 1) * NN);

    float a0 = 0.f, a1 = 0.f, a2 = 0.f, a3 = 0.f, a4 = 0.f;
    float b0 = 0.f, b1 = 0.f, b2 = 0.f, b3 = 0.f, b4 = 0.f;
    #pragma unroll 4
    for (int i = lane; i < NN / 4; i += 32) {
        float4 p = p4[i];
        float4 q = q4[i];
        {
            __half2 h0 = __floats2half2_rn(p.x, p.y);
            __half2 h1 = __floats2half2_rn(p.z, p.w);
            uint2 st;
            st.x = *(uint32_t*)&h0; st.y = *(uint32_t*)&h1;
            hp[i] = st;
            __half2 g0 = __floats2half2_rn(q.x, q.y);
            __half2 g1 = __floats2half2_rn(q.z, q.w);
            st.x = *(uint32_t*)&g0; st.y = *(uint32_t*)&g1;
            hq[i] = st;
        }
        float4 w = *(const float4*)&sw[0][i * 4];
        a0 = fmaf(p.x, w.x, a0); a0 = fmaf(p.y, w.y, a0);
        a0 = fmaf(p.z, w.z, a0); a0 = fmaf(p.w, w.w, a0);
        b0 = fmaf(q.x, w.x, b0); b0 = fmaf(q.y, w.y, b0);
        b0 = fmaf(q.z, w.z, b0); b0 = fmaf(q.w, w.w, b0);
        float4 e = *(const float4*)&sw[1][i * 4];
        a1 = fmaf(p.x, e.x, a1); a1 = fmaf(p.y, e.y, a1);
        a1 = fmaf(p.z, e.z, a1); a1 = fmaf(p.w, e.w, a1);
        b1 = fmaf(q.x, e.x, b1); b1 = fmaf(q.y, e.y, b1);
        b1 = fmaf(q.z, e.z, b1); b1 = fmaf(q.w, e.w, b1);
        float4 s = *(const float4*)&sw[2][i * 4];
        a2 = fmaf(p.x, s.x, a2); a2 = fmaf(p.y, s.y, a2);
        a2 = fmaf(p.z, s.z, a2); a2 = fmaf(p.w, s.w, a2);
        b2 = fmaf(q.x, s.x, b2); b2 = fmaf(q.y, s.y, b2);
        b2 = fmaf(q.z, s.z, b2); b2 = fmaf(q.w, s.w, b2);
        float4 c = *(const float4*)&sw[3][i * 4];
        a3 = fmaf(p.x, c.x, a3); a3 = fmaf(p.y, c.y, a3);
        a3 = fmaf(p.z, c.z, a3); a3 = fmaf(p.w, c.w, a3);
        b3 = fmaf(q.x, c.x, b3); b3 = fmaf(q.y, c.y, b3);
        b3 = fmaf(q.z, c.z, b3); b3 = fmaf(q.w, c.w, b3);
        float4 m = *(const float4*)&sw[4][i * 4];
        a4 = fmaf(p.x, m.x, a4); a4 = fmaf(p.y, m.y, a4);
        a4 = fmaf(p.z, m.z, a4); a4 = fmaf(p.w, m.w, a4);
        b4 = fmaf(q.x, m.x, b4); b4 = fmaf(q.y, m.y, b4);
        b4 = fmaf(q.z, m.z, b4); b4 = fmaf(q.w, m.w, b4);
    }
    #pragma unroll
    for (int o = 16; o > 0; o >>= 1) {
        a0 += __shfl_xor_sync(0xFFFFFFFFu, a0, o);
        a1 += __shfl_xor_sync(0xFFFFFFFFu, a1, o);
        a2 += __shfl_xor_sync(0xFFFFFFFFu, a2, o);
        a3 += __shfl_xor_sync(0xFFFFFFFFu, a3, o);
        a4 += __shfl_xor_sync(0xFFFFFFFFu, a4, o);
        b0 += __shfl_xor_sync(0xFFFFFFFFu, b0, o);
        b1 += __shfl_xor_sync(0xFFFFFFFFu, b1, o);
        b2 += __shfl_xor_sync(0xFFFFFFFFu, b2, o);
        b3 += __shfl_xor_sync(0xFFFFFFFFu, b3, o);
        b4 += __shfl_xor_sync(0xFFFFFFFFu, b4, o);
    }
    if (lane == 0) {
        #pragma unroll
        for (int rr = 0; rr < 2; rr++) {
            int   row = row0 + rr;
            int   h   = row % HH;
            float s0  = rr ? b0 : a0;
            float s1  = rr ? b1 : a1;
            float s2  = rr ? b2 : a2;
            float s3  = rr ? b3 : a3;
            float s4v = rr ? b4 : a4;

            float inv = 1.f / (s0 + EPSV);
            bool  pc  = (h < NN) && (is_track[b * NN + h] != 0);
            float nm  = pc ? 0.f : 1.f;

            float ke  = log1pf(fmaxf(s0, 0.f));
            float eta = s1 * inv * (1.f / 3.0f);
            float ph  = atan2f(s2 * inv, s3 * inv);
            float em  = s4v * inv;

            long long r3 = (long long)row * 3;
            float cpt = 0.f, ceta = 0.f, cphi = 0.f;
            if (pc) {
                cpt  = track_pt [b * NN + h];
                ceta = track_eta[b * NN + h];
                cphi = track_phi[b * NN + h];
            }
            out[OFF_CH + r3 + 0] = cpt;
            out[OFF_CH + r3 + 1] = ceta;
            out[OFF_CH + r3 + 2] = cphi;
            out[OFF_NEUT + r3 + 0] = ke  * nm;
            out[OFF_NEUT + r3 + 1] = eta * nm;
            out[OFF_NEUT + r3 + 2] = ph  * nm;
            out[OFF_PC + row] = pc ? 1.f : 0.f;
            out[OFF_EM + row] = em;
        }
    }
}

// ---------------------------------------------------------------------------
// 3) fp16 mma GEMM with ldmatrix + register fragment double-buffering:
//    block 128x128, BK=64 halfs, 128 threads (4 warps, 2x2, warp tile 64x64),
//    2-stage cp.async, 72 KB smem, 2 CTAs/SM.
//    Fragments for kk+16 are prefetched while kk's 32 mmas execute.
// ---------------------------------------------------------------------------
#define BM 128
#define BN 128
#define BKH 64
#define KPAD 72                     // halfs per smem row (144 B)
#define A_H (BM * KPAD)             // 9216 halfs
#define B_H (BN * KPAD)
#define STG_H (A_H + B_H)           // 18432 halfs = 36 KB / stage
#define GEMM_SMEM (2 * STG_H * 2)   // 73728 B

__global__ __launch_bounds__(128, 2)
void gemm_mma_kernel(float* __restrict__ C) {   // [B][H][D]
    extern __shared__ __align__(16) __half smem[];

    int tid  = threadIdx.x;
    int wid  = tid >> 5;
    int lane = tid & 31;
    int gid  = lane >> 2;
    int tig  = lane & 3;
    int warp_m = wid & 1;
    int warp_n = wid >> 1;
    int q  = lane >> 3;   // ldmatrix quadrant
    int rr = lane & 7;

    int b  = blockIdx.z;
    int m0 = blockIdx.y * BM;
    int n0 = blockIdx.x * BN;

    const __half* Ah = g_ah + ((size_t)b * HH + m0) * NN;
    const __half* Bh = g_bh + ((size_t)b * DD + n0) * NN;

    int lr = tid >> 3;   // 0..15 (+16 per pass, 8 passes over 128 rows)
    int lj = tid & 7;    // 8-half chunk within 64-half row

    uint32_t a_off = (uint32_t)(((warp_m * 64 + (q & 1) * 8 + rr) * KPAD + (q >> 1) * 8) * 2);
    uint32_t b_off = (uint32_t)(((warp_n * 64 + (q >> 1) * 8 + rr) * KPAD + (q & 1) * 8) * 2);

    float acc[4][8][4];
    #pragma unroll
    for (int i = 0; i < 4; i++)
        #pragma unroll
        for (int j = 0; j < 8; j++)
            #pragma unroll
            for (int k = 0; k < 4; k++) acc[i][j][k] = 0.f;

    auto load_tile = [&](int t, int s) {
        __half* asx = smem + s * STG_H;
        __half* bsx = asx + A_H;
        int k0 = t * BKH;
        #pragma unroll
        for (int i = 0; i < 8; i++) {
            int r = lr + i * 16;
            cp16(smem_u32(asx + r * KPAD + lj * 8), Ah + (size_t)r * NN + k0 + lj * 8);
            cp16(smem_u32(bsx + r * KPAD + lj * 8), Bh + (size_t)r * NN + k0 + lj * 8);
        }
        cp_commit();
    };

    load_tile(0, 0);

    uint32_t af[2][4][4];
    uint32_t bf[2][8][2];

    auto load_frags = [&](uint32_t as_u, uint32_t bs_u, int kk, int buf) {
        #pragma unroll
        for (int nf2 = 0; nf2 < 4; nf2++) {
            uint32_t r0, r1, r2, r3;
            LDSM_X4(r0, r1, r2, r3,
                    bs_u + b_off + (uint32_t)((nf2 * 16 * KPAD + kk) * 2));
            bf[buf][2 * nf2][0]     = r0;
            bf[buf][2 * nf2][1]     = r1;
            bf[buf][2 * nf2 + 1][0] = r2;
            bf[buf][2 * nf2 + 1][1] = r3;
        }
        #pragma unroll
        for (int mf = 0; mf < 4; mf++) {
            LDSM_X4(af[buf][mf][0], af[buf][mf][1], af[buf][mf][2], af[buf][mf][3],
                    as_u + a_off + (uint32_t)((mf * 16 * KPAD + kk) * 2));
        }
    };

    const int NT = NN / BKH;  // 16
    for (int t = 0; t < NT; t++) {
        if (t + 1 < NT) {
            load_tile(t + 1, (t + 1) & 1);
            cp_wait<1>();
        } else {
            cp_wait<0>();
        }
        __syncthreads();

        uint32_t as_u = smem_u32(smem + (t & 1) * STG_H);
        uint32_t bs_u = as_u + A_H * 2;

        load_frags(as_u, bs_u, 0, 0);
        #pragma unroll
        for (int ki = 0; ki < BKH / 16; ki++) {     // 4 kk steps
            int cur = ki & 1;
            if (ki + 1 < BKH / 16)
                load_frags(as_u, bs_u, (ki + 1) * 16, cur ^ 1);
            #pragma unroll
            for (int mf = 0; mf < 4; mf++)
                #pragma unroll
                for (int nf = 0; nf < 8; nf++)
                    mma_f16(acc[mf][nf], af[cur][mf], bf[cur][nf]);
        }
        __syncthreads();
    }

    // Epilogue
    float* Cb = C + ((size_t)b * HH + m0) * DD + n0;
    #pragma unroll
    for (int mf = 0; mf < 4; mf++) {
        int r0 = warp_m * 64 + mf * 16 + gid;
        #pragma unroll
        for (int nf = 0; nf < 8; nf++) {
            int cc = warp_n * 64 + nf * 8 + tig * 2;
            *(float2*)(Cb + (size_t)r0 * DD + cc) =
                make_float2(acc[mf][nf][0], acc[mf][nf][1]);
            *(float2*)(Cb + (size_t)(r0 + 8) * DD + cc) =
                make_float2(acc[mf][nf][2], acc[mf][nf][3]);
        }
    }
}

// ---------------------------------------------------------------------------
extern "C" void kernel_launch(void* const* d_in, const int* in_sizes, int n_in,
                              void* d_out, int out_size) {
    const float* pred_inc  = (const float*)d_in[0];
    const float* node_feat = (const float*)d_in[1];
    const float* e_raw     = (const float*)d_in[2];
    const float* eta_raw   = (const float*)d_in[3];
    const float* phi       = (const float*)d_in[4];
    const float* em_frac   = (const float*)d_in[5];
    const float* track_pt  = (const float*)d_in[6];
    const float* track_eta = (const float*)d_in[7];
    const float* track_phi = (const float*)d_in[8];
    const int*   is_track  = (const int*)d_in[9];
    const int*   is_topo   = (const int*)d_in[10];
    float* out = (float*)d_out;

    cudaFuncSetAttribute(gemm_mma_kernel,
                         cudaFuncAttributeMaxDynamicSharedMemorySize, GEMM_SMEM);

    {
        dim3 grid(NN / 64, DD / 32, BB);
        transpose_kernel<<<grid, dim3(32, 8)>>>(node_feat);
    }
    nfs_final_kernel<<<BB, DD>>>(out);

    {
        dim3 grid(HH / 16, BB);
        row_kernel<<<grid, 256>>>(pred_inc, e_raw, eta_raw, phi, em_frac, is_topo,
                                  track_pt, track_eta, track_phi, is_track, out);
    }

    {
        dim3 grid(DD / BN, HH / BM, BB);
        gemm_mma_kernel<<<grid, 128, GEMM_SMEM>>>(out + OFF_MM);
    }
}